// round 7
// baseline (speedup 1.0000x reference)
#include <cuda_runtime.h>
#include <math.h>

// ---------------- problem constants ----------------
#define Bc    2
#define Tc    1024
#define Ec    1024
#define Hc    16
#define Dc    64
#define NRELc 529
#define BHc   (Bc*Hc)
#define FFc   (4*Ec)
#define INV_SQRT_D 0.125f
#define INV_SQRT3  0.57735026918962576451f   // 1/sqrt(args.sqrt=3)

// ---------------- scratch (device globals; allocation-free) ----------------
__device__ float g_h1 [Bc*Tc*Ec];          // 8 MB   ln1 output
__device__ float g_qkv[Bc*Tc*3*Ec];        // 24 MB
__device__ float g_q  [BHc*Tc*Dc];         // 8 MB   [b,h,t,d]
__device__ float g_k  [BHc*Tc*Dc];
__device__ float g_v  [BHc*Tc*Dc];
__device__ float g_w  [BHc*Tc*Tc];         // 128 MB scores -> probs (in place)
__device__ float g_qrk[BHc*Tc*65];         // q . rel_keys table
__device__ float g_lr1[BHc*Tc*NRELc];      // 69 MB  q . LR_K^T  (scaled)
__device__ float g_lr2[BHc*NRELc*Tc];      // 69 MB  LR_Q . k^T  (scaled)
__device__ float g_ret[BHc*Tc*Dc];         // p @ v
__device__ float g_af [Bc*Tc*Ec];          // merged heads (+relv term)
__device__ float g_x2 [Bc*Tc*Ec];          // x + attn
__device__ float g_h2 [Bc*Tc*Ec];          // ln2 output
__device__ float g_fc [Bc*Tc*FFc];         // 32 MB  gelu(fc)

// ---------------- helpers ----------------
__device__ __forceinline__ float warp_sum(float v) {
    #pragma unroll
    for (int o = 16; o; o >>= 1) v += __shfl_xor_sync(0xffffffffu, v, o);
    return v;
}
__device__ __forceinline__ float warp_max(float v) {
    #pragma unroll
    for (int o = 16; o; o >>= 1) v = fmaxf(v, __shfl_xor_sync(0xffffffffu, v, o));
    return v;
}
__device__ __forceinline__ float gelu_f(float v) {
    const float c = 0.7978845608028654f;  // sqrt(2/pi)
    float t = tanhf(c * (v + 0.044715f * v * v * v));
    return 0.5f * v * (1.f + t);
}

// ---------------- LayerNorm (TF-style, ddof=1, eps added to std) ----------------
__global__ __launch_bounds__(256) void ln_kernel(
    const float* __restrict__ x, const float* __restrict__ gw,
    const float* __restrict__ gb, float* __restrict__ out)
{
    int row = blockIdx.x;                       // B*T rows
    const float4* xr = (const float4*)(x + (size_t)row * Ec);
    float4 v = xr[threadIdx.x];                 // 256 threads * 4 = 1024
    __shared__ float red[8];
    __shared__ float bval[2];
    int wid = threadIdx.x >> 5, lane = threadIdx.x & 31;

    float s = warp_sum(v.x + v.y + v.z + v.w);
    if (lane == 0) red[wid] = s;
    __syncthreads();
    if (threadIdx.x == 0) {
        float t = 0.f;
        #pragma unroll
        for (int i = 0; i < 8; i++) t += red[i];
        bval[0] = t * (1.f / Ec);
    }
    __syncthreads();
    float mean = bval[0];
    float d0 = v.x - mean, d1 = v.y - mean, d2 = v.z - mean, d3 = v.w - mean;
    float q = warp_sum(d0*d0 + d1*d1 + d2*d2 + d3*d3);
    if (lane == 0) red[wid] = q;
    __syncthreads();
    if (threadIdx.x == 0) {
        float t = 0.f;
        #pragma unroll
        for (int i = 0; i < 8; i++) t += red[i];
        bval[1] = 1.f / (sqrtf(t / (float)(Ec - 1)) + 1e-6f);  // unbiased std + eps
    }
    __syncthreads();
    float inv = bval[1];
    float4 ww = ((const float4*)gw)[threadIdx.x];
    float4 bb = ((const float4*)gb)[threadIdx.x];
    float4 o;
    o.x = ww.x * d0 * inv + bb.x;
    o.y = ww.y * d1 * inv + bb.y;
    o.z = ww.z * d2 * inv + bb.z;
    o.w = ww.w * d3 * inv + bb.w;
    ((float4*)(out + (size_t)row * Ec))[threadIdx.x] = o;
}

// ---------------- generic SGEMM: C = act(A[M,K] @ B[K,N] + bias [+ resid]) ----------------
// 128x128 tile, BK=8, 256 threads, 8x8 per thread. M,N,K multiples of 128/128/8.
template<int MODE>   // 0: bias  1: bias+gelu  2: bias+residual
__global__ __launch_bounds__(256) void sgemm_kernel(
    const float* __restrict__ A, const float* __restrict__ Bm,
    const float* __restrict__ bias, const float* __restrict__ resid,
    float* __restrict__ C, int M, int N, int K)
{
    __shared__ float As[8][128];
    __shared__ float Bs[8][128];
    int bm = blockIdx.y * 128, bn = blockIdx.x * 128;
    int tid = threadIdx.x;
    int arow = tid >> 1, acol = (tid & 1) * 4;
    int brow = tid >> 5, bcol = (tid & 31) * 4;
    int ty = tid >> 4, tx = tid & 15;
    float acc[8][8] = {};

    for (int k0 = 0; k0 < K; k0 += 8) {
        float4 a = *(const float4*)(A + (size_t)(bm + arow) * K + k0 + acol);
        As[acol+0][arow] = a.x; As[acol+1][arow] = a.y;
        As[acol+2][arow] = a.z; As[acol+3][arow] = a.w;
        float4 b4 = *(const float4*)(Bm + (size_t)(k0 + brow) * N + bn + bcol);
        *(float4*)&Bs[brow][bcol] = b4;
        __syncthreads();
        #pragma unroll
        for (int kk = 0; kk < 8; kk++) {
            float af[8], bf[8];
            *(float4*)&af[0] = *(const float4*)&As[kk][ty*8];
            *(float4*)&af[4] = *(const float4*)&As[kk][ty*8+4];
            *(float4*)&bf[0] = *(const float4*)&Bs[kk][tx*8];
            *(float4*)&bf[4] = *(const float4*)&Bs[kk][tx*8+4];
            #pragma unroll
            for (int i = 0; i < 8; i++)
                #pragma unroll
                for (int j = 0; j < 8; j++)
                    acc[i][j] = fmaf(af[i], bf[j], acc[i][j]);
        }
        __syncthreads();
    }
    #pragma unroll
    for (int i = 0; i < 8; i++) {
        int m = bm + ty*8 + i;
        #pragma unroll
        for (int j = 0; j < 8; j++) {
            int n = bn + tx*8 + j;
            float c = acc[i][j] + bias[n];
            if (MODE == 1) c = gelu_f(c);
            if (MODE == 2) c += resid[(size_t)m * N + n];
            C[(size_t)m * N + n] = c;
        }
    }
}

// ---------------- split qkv buffer into head-major q/k/v ----------------
__global__ __launch_bounds__(256) void split_qkv_kernel()
{
    int idx = blockIdx.x * 256 + threadIdx.x;         // over B*T*3E
    int c = idx % (3 * Ec);
    int rowbt = idx / (3 * Ec);
    int which = c >> 10;                // /E
    int e = c & (Ec - 1);
    int h = e >> 6, d = e & 63;
    int b = rowbt >> 10, t = rowbt & (Tc - 1);
    float val = g_qkv[idx];
    float* dst = (which == 0) ? g_q : ((which == 1) ? g_k : g_v);
    dst[(((size_t)(b * Hc + h)) * Tc + t) * Dc + d] = val;
}

// ---------------- batched NT GEMM: C[bh][M,N] = scale * A[M,64] @ B[N,64]^T ----------------
__global__ __launch_bounds__(256) void ntgemm_kernel(
    const float* __restrict__ A, int strideA, int aModH,
    const float* __restrict__ Bm, int strideB, int bModH,
    float* __restrict__ C, size_t strideC, int M, int N, float scale)
{
    int bh = blockIdx.z;
    const float* Ab = A  + (size_t)(aModH ? (bh % Hc) : bh) * strideA;
    const float* Bb = Bm + (size_t)(bModH ? (bh % Hc) : bh) * strideB;
    float* Cb = C + (size_t)bh * strideC;
    int m0 = blockIdx.y * 64, n0 = blockIdx.x * 64;
    __shared__ float As[64][68];   // [k][m]
    __shared__ float Bs[64][68];   // [k][n]
    int tid = threadIdx.x;
    int tr = tid >> 4, tc4 = (tid & 15) * 4;
    #pragma unroll
    for (int p = 0; p < 4; p++) {
        int r = p * 16 + tr;
        float4 a = make_float4(0.f, 0.f, 0.f, 0.f);
        if (m0 + r < M) a = *(const float4*)(Ab + (size_t)(m0 + r) * Dc + tc4);
        As[tc4+0][r] = a.x; As[tc4+1][r] = a.y; As[tc4+2][r] = a.z; As[tc4+3][r] = a.w;
        float4 b4 = make_float4(0.f, 0.f, 0.f, 0.f);
        if (n0 + r < N) b4 = *(const float4*)(Bb + (size_t)(n0 + r) * Dc + tc4);
        Bs[tc4+0][r] = b4.x; Bs[tc4+1][r] = b4.y; Bs[tc4+2][r] = b4.z; Bs[tc4+3][r] = b4.w;
    }
    __syncthreads();
    int ty = tid >> 4, tx = tid & 15;
    float acc[4][4] = {};
    #pragma unroll
    for (int k = 0; k < 64; k++) {
        float af[4], bf[4];
        *(float4*)af = *(const float4*)&As[k][ty*4];
        *(float4*)bf = *(const float4*)&Bs[k][tx*4];
        #pragma unroll
        for (int i = 0; i < 4; i++)
            #pragma unroll
            for (int j = 0; j < 4; j++)
                acc[i][j] = fmaf(af[i], bf[j], acc[i][j]);
    }
    #pragma unroll
    for (int i = 0; i < 4; i++) {
        int m = m0 + ty*4 + i;
        if (m >= M) continue;
        #pragma unroll
        for (int j = 0; j < 4; j++) {
            int n = n0 + tx*4 + j;
            if (n < N) Cb[(size_t)m * N + n] = acc[i][j] * scale;
        }
    }
}

// ---------------- causal scores + full epilogue ----------------
// w[i,j] = ((q.k + qrk)*inv_sqrt_d * relw[rel] + tds + lr1[lm] + lr2[lm]) / sqrt(3)
__global__ __launch_bounds__(256) void scores_kernel(
    const float* __restrict__ tds, const int* __restrict__ rel,
    const int* __restrict__ lrmap, const float* __restrict__ relw)
{
    int it = blockIdx.y, jt = blockIdx.x;
    if (jt > it) return;                       // strictly causal tiles only
    int bh = blockIdx.z;
    int b = bh >> 4, h = bh & 15;
    int i0 = it * 64, j0 = jt * 64;
    const float* Aq = g_q + (size_t)bh * Tc * Dc;
    const float* Bk = g_k + (size_t)bh * Tc * Dc;
    __shared__ float As[64][68];
    __shared__ float Bs[64][68];
    int tid = threadIdx.x;
    int tr = tid >> 4, tc4 = (tid & 15) * 4;
    #pragma unroll
    for (int p = 0; p < 4; p++) {
        int r = p * 16 + tr;
        float4 a = *(const float4*)(Aq + (size_t)(i0 + r) * Dc + tc4);
        As[tc4+0][r] = a.x; As[tc4+1][r] = a.y; As[tc4+2][r] = a.z; As[tc4+3][r] = a.w;
        float4 kq = *(const float4*)(Bk + (size_t)(j0 + r) * Dc + tc4);
        Bs[tc4+0][r] = kq.x; Bs[tc4+1][r] = kq.y; Bs[tc4+2][r] = kq.z; Bs[tc4+3][r] = kq.w;
    }
    __syncthreads();
    int ty = tid >> 4, tx = tid & 15;
    float acc[4][4] = {};
    #pragma unroll
    for (int k = 0; k < 64; k++) {
        float af[4], bf[4];
        *(float4*)af = *(const float4*)&As[k][ty*4];
        *(float4*)bf = *(const float4*)&Bs[k][tx*4];
        #pragma unroll
        for (int i = 0; i < 4; i++)
            #pragma unroll
            for (int j = 0; j < 4; j++)
                acc[i][j] = fmaf(af[i], bf[j], acc[i][j]);
    }
    #pragma unroll
    for (int ii = 0; ii < 4; ii++) {
        int i = i0 + ty*4 + ii;
        const float* qrk_row = g_qrk + ((size_t)bh * Tc + i) * 65;
        const float* lr1_row = g_lr1 + ((size_t)bh * Tc + i) * NRELc;
        size_t base_b  = ((size_t)b  * Tc + i) * Tc;
        size_t base_bh = ((size_t)bh * Tc + i) * Tc;
        #pragma unroll
        for (int jj = 0; jj < 4; jj++) {
            int j = j0 + tx*4 + jj;
            if (j > i) continue;
            int rid = j - i + 32; if (rid < 0) rid = 0;   // clip(j-i,-32,32)+32, j<=i
            float wv = (acc[ii][jj] + qrk_row[rid]) * INV_SQRT_D;
            wv *= relw[rel[base_b + j] * Hc + h];          // multiplicative tree rel
            wv += tds[base_bh + j];
            int lm = lrmap[base_b + j];
            wv = (wv + lr1_row[lm] + g_lr2[((size_t)bh * NRELc + lm) * Tc + j]) * INV_SQRT3;
            g_w[base_bh + j] = wv;
        }
    }
}

// ---------------- causal softmax (in place, only j<=i touched) ----------------
__global__ __launch_bounds__(128) void softmax_kernel()
{
    int row = blockIdx.x;               // bh*T + i
    int i = row & (Tc - 1);
    float* wr = g_w + (size_t)row * Tc;
    int len = i + 1;
    int wid = threadIdx.x >> 5, lane = threadIdx.x & 31;
    __shared__ float sm[4], sm2[4];

    float mx = -1e30f;
    for (int j = threadIdx.x; j < len; j += 128) mx = fmaxf(mx, wr[j]);
    mx = warp_max(mx);
    if (lane == 0) sm[wid] = mx;
    __syncthreads();
    mx = fmaxf(fmaxf(sm[0], sm[1]), fmaxf(sm[2], sm[3]));

    float s = 0.f;
    for (int j = threadIdx.x; j < len; j += 128) {
        float e = __expf(wr[j] - mx);
        wr[j] = e;
        s += e;
    }
    s = warp_sum(s);
    if (lane == 0) sm2[wid] = s;
    __syncthreads();
    float inv = 1.f / (sm2[0] + sm2[1] + sm2[2] + sm2[3]);
    for (int j = threadIdx.x; j < len; j += 128) wr[j] *= inv;
}

// ---------------- causal p @ v  -> g_ret ----------------
__global__ __launch_bounds__(256) void pv_kernel()
{
    int bh = blockIdx.z;
    int it = blockIdx.y;
    int i0 = it * 64;
    __shared__ float Ps[64][68];   // [j][i]
    __shared__ float Vs[64][68];   // [j][d]
    int tid = threadIdx.x;
    int tr = tid >> 4, tc4 = (tid & 15) * 4;
    int ty = tid >> 4, tx = tid & 15;
    float acc[4][4] = {};
    const float* Vb = g_v + (size_t)bh * Tc * Dc;

    for (int jt = 0; jt <= it; jt++) {
        int j0 = jt * 64;
        #pragma unroll
        for (int p = 0; p < 4; p++) {
            int r = p * 16 + tr;
            int i = i0 + r;
            float4 pv4 = *(const float4*)(g_w + ((size_t)bh * Tc + i) * Tc + j0 + tc4);
            int jb = j0 + tc4;
            Ps[tc4+0][r] = (jb + 0 <= i) ? pv4.x : 0.f;   // zero upper triangle
            Ps[tc4+1][r] = (jb + 1 <= i) ? pv4.y : 0.f;
            Ps[tc4+2][r] = (jb + 2 <= i) ? pv4.z : 0.f;
            Ps[tc4+3][r] = (jb + 3 <= i) ? pv4.w : 0.f;
            float4 vv = *(const float4*)(Vb + (size_t)(j0 + r) * Dc + tc4);
            *(float4*)&Vs[r][tc4] = vv;
        }
        __syncthreads();
        #pragma unroll
        for (int k = 0; k < 64; k++) {
            float af[4], bf[4];
            *(float4*)af = *(const float4*)&Ps[k][ty*4];
            *(float4*)bf = *(const float4*)&Vs[k][tx*4];
            #pragma unroll
            for (int i2 = 0; i2 < 4; i2++)
                #pragma unroll
                for (int j2 = 0; j2 < 4; j2++)
                    acc[i2][j2] = fmaf(af[i2], bf[j2], acc[i2][j2]);
        }
        __syncthreads();
    }
    #pragma unroll
    for (int i2 = 0; i2 < 4; i2++)
        #pragma unroll
        for (int j2 = 0; j2 < 4; j2++)
            g_ret[((size_t)bh * Tc + i0 + ty*4 + i2) * Dc + tx*4 + j2] = acc[i2][j2];
}

// ---------------- relv term + merge heads -> g_af ----------------
// p.relv collapses: rid(j)=clip(j-i)+32; rid in [1,32] hit exactly one j (= i-32+r),
// rid=0 aggregates all j<=i-32 with weight (1 - sum of last-32 probs).
__global__ __launch_bounds__(64) void relv_merge_kernel(const float* __restrict__ rv)
{
    int row = blockIdx.x;              // bh*T + i
    int i = row & (Tc - 1);
    int bh = row >> 10;
    int b = bh >> 4, h = bh & 15;
    __shared__ float pl[32];
    if (threadIdx.x < 32) {
        int j = i - 31 + (int)threadIdx.x;          // r = lane+1  (j = i-32+r)
        pl[threadIdx.x] = (j >= 0) ? g_w[(size_t)row * Tc + j] : 0.f;
    }
    __syncthreads();
    int d = threadIdx.x;
    float s32 = 0.f, contrib = 0.f;
    #pragma unroll
    for (int l = 0; l < 32; l++) {
        float p = pl[l];
        s32 += p;
        contrib = fmaf(p, rv[(l + 1) * Dc + d], contrib);
    }
    contrib = fmaf(1.f - s32, rv[d], contrib);      // far-sum * rel_values[0]
    float val = g_ret[(size_t)row * Dc + d] + contrib;
    g_af[((size_t)(b * Tc + i)) * Ec + h * Dc + d] = val;
}

// ---------------- host ----------------
extern "C" void kernel_launch(void* const* d_in, const int* in_sizes, int n_in,
                              void* d_out, int out_size)
{
    // Runtime detection of input ordering:
    //  dict order:      x,tds,LR_Q,LR_K,rel,LR_map,Wqkv,bqkv,Wproj,bproj,relw,relk,relv,ln1w,ln1b,ln2w,ln2b,Wfc,bfc,Wfp,bfp
    //  signature order: x,tds,LR_Q,LR_K,Wqkv,bqkv,Wproj,bproj,relw,relk,relv,ln1w,ln1b,ln2w,ln2b,Wfc,bfc,Wfp,bfp,rel,LR_map
    int ix, itds, ilrq, ilrk, irel, ilrm, iwqkv, ibqkv, iwpr, ibpr, irlw, irlk, irlv,
        il1w, il1b, il2w, il2b, iwfc, ibfc, iwfp, ibfp;
    if (in_sizes[4] == 3 * 1024 * 1024) {   // Wqkv at slot 4 => signature order
        ix=0; itds=1; ilrq=2; ilrk=3; iwqkv=4; ibqkv=5; iwpr=6; ibpr=7; irlw=8; irlk=9; irlv=10;
        il1w=11; il1b=12; il2w=13; il2b=14; iwfc=15; ibfc=16; iwfp=17; ibfp=18; irel=19; ilrm=20;
    } else {                                 // dict order
        ix=0; itds=1; ilrq=2; ilrk=3; irel=4; ilrm=5; iwqkv=6; ibqkv=7; iwpr=8; ibpr=9; irlw=10;
        irlk=11; irlv=12; il1w=13; il1b=14; il2w=15; il2b=16; iwfc=17; ibfc=18; iwfp=19; ibfp=20;
    }
    const float* x    = (const float*)d_in[ix];
    const float* tds  = (const float*)d_in[itds];
    const float* LRQ  = (const float*)d_in[ilrq];
    const float* LRK  = (const float*)d_in[ilrk];
    const int*   rel  = (const int*)  d_in[irel];
    const int*   lrm  = (const int*)  d_in[ilrm];
    const float* Wqkv = (const float*)d_in[iwqkv];
    const float* bqkv = (const float*)d_in[ibqkv];
    const float* Wpr  = (const float*)d_in[iwpr];
    const float* bpr  = (const float*)d_in[ibpr];
    const float* relw = (const float*)d_in[irlw];
    const float* relk = (const float*)d_in[irlk];
    const float* relv = (const float*)d_in[irlv];
    const float* l1w  = (const float*)d_in[il1w];
    const float* l1b  = (const float*)d_in[il1b];
    const float* l2w  = (const float*)d_in[il2w];
    const float* l2b  = (const float*)d_in[il2b];
    const float* Wfc  = (const float*)d_in[iwfc];
    const float* bfc  = (const float*)d_in[ibfc];
    const float* Wfp  = (const float*)d_in[iwfp];
    const float* bfp  = (const float*)d_in[ibfp];
    float* out = (float*)d_out;

    float *p_h1, *p_qkv, *p_q, *p_k, *p_qrk, *p_lr1, *p_lr2, *p_af, *p_x2, *p_h2, *p_fc;
    cudaGetSymbolAddress((void**)&p_h1,  g_h1);
    cudaGetSymbolAddress((void**)&p_qkv, g_qkv);
    cudaGetSymbolAddress((void**)&p_q,   g_q);
    cudaGetSymbolAddress((void**)&p_k,   g_k);
    cudaGetSymbolAddress((void**)&p_qrk, g_qrk);
    cudaGetSymbolAddress((void**)&p_lr1, g_lr1);
    cudaGetSymbolAddress((void**)&p_lr2, g_lr2);
    cudaGetSymbolAddress((void**)&p_af,  g_af);
    cudaGetSymbolAddress((void**)&p_x2,  g_x2);
    cudaGetSymbolAddress((void**)&p_h2,  g_h2);
    cudaGetSymbolAddress((void**)&p_fc,  g_fc);

    const int M = Bc * Tc;   // 2048

    // 1) LN1
    ln_kernel<<<M, 256>>>(x, l1w, l1b, p_h1);
    // 2) QKV GEMM + split into head-major q/k/v
    sgemm_kernel<0><<<dim3(3072/128, M/128), 256>>>(p_h1, Wqkv, bqkv, nullptr, p_qkv, M, 3072, 1024);
    split_qkv_kernel<<<(Bc*Tc*3*Ec)/256, 256>>>();
    // 3) qrk table: q . rel_keys^T  (unscaled; scale applied with qk)
    ntgemm_kernel<<<dim3(2, Tc/64, BHc), 256>>>(p_q, Tc*Dc, 0, relk, 0, 0,
                                                p_qrk, (size_t)Tc*65, Tc, 65, 1.0f);
    // 4) lr1 = (q . LR_K^T) * inv_sqrt_d
    ntgemm_kernel<<<dim3((NRELc+63)/64, Tc/64, BHc), 256>>>(p_q, Tc*Dc, 0, LRK, NRELc*Dc, 1,
                                                p_lr1, (size_t)Tc*NRELc, Tc, NRELc, INV_SQRT_D);
    // 5) lr2 = (LR_Q . k^T) * inv_sqrt_d
    ntgemm_kernel<<<dim3(Tc/64, (NRELc+63)/64, BHc), 256>>>(LRQ, NRELc*Dc, 1, p_k, Tc*Dc, 0,
                                                p_lr2, (size_t)NRELc*Tc, NRELc, Tc, INV_SQRT_D);
    // 6) causal scores + epilogue
    scores_kernel<<<dim3(Tc/64, Tc/64, BHc), 256>>>(tds, rel, lrm, relw);
    // 7) causal softmax (in place)
    softmax_kernel<<<BHc*Tc, 128>>>();
    // 8) p @ v
    pv_kernel<<<dim3(1, Tc/64, BHc), 256>>>();
    // 9) + p @ relv  (collapsed) + merge heads
    relv_merge_kernel<<<BHc*Tc, 64>>>(relv);
    // 10) proj + residual -> x2
    sgemm_kernel<2><<<dim3(1024/128, M/128), 256>>>(p_af, Wpr, bpr, x, p_x2, M, 1024, 1024);
    // 11) LN2
    ln_kernel<<<M, 256>>>(p_x2, l2w, l2b, p_h2);
    // 12) FC + gelu
    sgemm_kernel<1><<<dim3(4096/128, M/128), 256>>>(p_h2, Wfc, bfc, nullptr, p_fc, M, 4096, 1024);
    // 13) FP + bias + residual -> out
    sgemm_kernel<2><<<dim3(1024/128, M/128), 256>>>(p_fc, Wfp, bfp, p_x2, out, M, 1024, 4096);
}

// round 9
// speedup vs baseline: 1.8525x; 1.8525x over previous
#include <cuda_runtime.h>
#include <cuda_bf16.h>
#include <math.h>
#include <stdint.h>

// ---------------- problem constants ----------------
#define Bc    2
#define Tc    1024
#define Ec    1024
#define Hc    16
#define Dc    64
#define NRELc 529
#define BHc   (Bc*Hc)
#define FFc   (4*Ec)
#define INV_SQRT_D 0.125f
#define INV_SQRT3  0.57735026918962576451f

// ---------------- scratch (device globals; allocation-free) ----------------
__device__ float g_qkv[Bc*Tc*3*Ec];
__device__ float g_q  [BHc*Tc*Dc];
__device__ float g_k  [BHc*Tc*Dc];
__device__ float g_v  [BHc*Tc*Dc];
__device__ float g_w  [BHc*Tc*Tc];
__device__ float g_qrk[BHc*Tc*65];
__device__ float g_lr1[BHc*Tc*NRELc];
__device__ float g_lr2[BHc*NRELc*Tc];
__device__ float g_ret[BHc*Tc*Dc];
__device__ float g_x2 [Bc*Tc*Ec];

__device__ __nv_bfloat16 g_actA_hi[Bc*Tc*Ec];
__device__ __nv_bfloat16 g_actA_lo[Bc*Tc*Ec];
__device__ __nv_bfloat16 g_actB_hi[Bc*Tc*FFc];
__device__ __nv_bfloat16 g_actB_lo[Bc*Tc*FFc];

#define WOFF_QKV 0
#define WOFF_PROJ (3072*1024)
#define WOFF_FC  (WOFF_PROJ + 1024*1024)
#define WOFF_FP  (WOFF_FC + 4096*1024)
#define WT_TOTAL (WOFF_FP + 1024*4096)
__device__ __nv_bfloat16 g_wt_hi[WT_TOTAL];
__device__ __nv_bfloat16 g_wt_lo[WT_TOTAL];

// ---------------- helpers ----------------
__device__ __forceinline__ float warp_sum(float v) {
    #pragma unroll
    for (int o = 16; o; o >>= 1) v += __shfl_xor_sync(0xffffffffu, v, o);
    return v;
}
__device__ __forceinline__ float warp_max(float v) {
    #pragma unroll
    for (int o = 16; o; o >>= 1) v = fmaxf(v, __shfl_xor_sync(0xffffffffu, v, o));
    return v;
}
__device__ __forceinline__ float gelu_f(float v) {
    const float c = 0.7978845608028654f;
    float t = tanhf(c * (v + 0.044715f * v * v * v));
    return 0.5f * v * (1.f + t);
}
__device__ __forceinline__ uint32_t smem_u32(const void* p) {
    uint32_t a;
    asm("{ .reg .u64 t; cvta.to.shared.u64 t, %1; cvt.u32.u64 %0, t; }" : "=r"(a) : "l"(p));
    return a;
}
__device__ __forceinline__ uint32_t pack_bf2(__nv_bfloat16 a, __nv_bfloat16 b) {
    __nv_bfloat162 t; t.x = a; t.y = b;
    return *(uint32_t*)&t;
}
__device__ __forceinline__ void ldsm4(uint32_t& r0, uint32_t& r1, uint32_t& r2, uint32_t& r3,
                                      uint32_t addr) {
    asm volatile("ldmatrix.sync.aligned.m8n8.x4.shared.b16 {%0,%1,%2,%3}, [%4];"
                 : "=r"(r0), "=r"(r1), "=r"(r2), "=r"(r3) : "r"(addr));
}
__device__ __forceinline__ void mma16816(float* d, uint32_t a0, uint32_t a1, uint32_t a2,
                                         uint32_t a3, uint32_t b0, uint32_t b1) {
    asm volatile(
        "mma.sync.aligned.m16n8k16.row.col.f32.bf16.bf16.f32 "
        "{%0,%1,%2,%3}, {%4,%5,%6,%7}, {%8,%9}, {%0,%1,%2,%3};"
        : "+f"(d[0]), "+f"(d[1]), "+f"(d[2]), "+f"(d[3])
        : "r"(a0), "r"(a1), "r"(a2), "r"(a3), "r"(b0), "r"(b1));
}

// ---------------- LayerNorm -> split-bf16 ----------------
__global__ __launch_bounds__(256) void ln_bf16_kernel(
    const float* __restrict__ x, const float* __restrict__ gw,
    const float* __restrict__ gb,
    __nv_bfloat16* __restrict__ ohi, __nv_bfloat16* __restrict__ olo)
{
    int row = blockIdx.x;
    const float4* xr = (const float4*)(x + (size_t)row * Ec);
    float4 v = xr[threadIdx.x];
    __shared__ float red[8];
    __shared__ float bval[2];
    int wid = threadIdx.x >> 5, lane = threadIdx.x & 31;

    float s = warp_sum(v.x + v.y + v.z + v.w);
    if (lane == 0) red[wid] = s;
    __syncthreads();
    if (threadIdx.x == 0) {
        float t = 0.f;
        #pragma unroll
        for (int i = 0; i < 8; i++) t += red[i];
        bval[0] = t * (1.f / Ec);
    }
    __syncthreads();
    float mean = bval[0];
    float d0 = v.x - mean, d1 = v.y - mean, d2 = v.z - mean, d3 = v.w - mean;
    float q = warp_sum(d0*d0 + d1*d1 + d2*d2 + d3*d3);
    if (lane == 0) red[wid] = q;
    __syncthreads();
    if (threadIdx.x == 0) {
        float t = 0.f;
        #pragma unroll
        for (int i = 0; i < 8; i++) t += red[i];
        bval[1] = 1.f / (sqrtf(t / (float)(Ec - 1)) + 1e-6f);
    }
    __syncthreads();
    float inv = bval[1];
    float4 ww = ((const float4*)gw)[threadIdx.x];
    float4 bb = ((const float4*)gb)[threadIdx.x];
    float o0 = ww.x * d0 * inv + bb.x;
    float o1 = ww.y * d1 * inv + bb.y;
    float o2 = ww.z * d2 * inv + bb.z;
    float o3 = ww.w * d3 * inv + bb.w;

    __nv_bfloat16 h0 = __float2bfloat16(o0), h1 = __float2bfloat16(o1),
                  h2 = __float2bfloat16(o2), h3 = __float2bfloat16(o3);
    __nv_bfloat16 l0 = __float2bfloat16(o0 - __bfloat162float(h0));
    __nv_bfloat16 l1 = __float2bfloat16(o1 - __bfloat162float(h1));
    __nv_bfloat16 l2 = __float2bfloat16(o2 - __bfloat162float(h2));
    __nv_bfloat16 l3 = __float2bfloat16(o3 - __bfloat162float(h3));
    size_t base = (size_t)row * Ec + threadIdx.x * 4;
    *(uint2*)(ohi + base) = make_uint2(pack_bf2(h0,h1), pack_bf2(h2,h3));
    *(uint2*)(olo + base) = make_uint2(pack_bf2(l0,l1), pack_bf2(l2,l3));
}

// ---------------- weight transpose + split-bf16:  W[K,N] -> [N,K] hi/lo ----------------
__global__ __launch_bounds__(256) void transpose_conv_kernel(
    const float* __restrict__ W,
    __nv_bfloat16* __restrict__ Ohi, __nv_bfloat16* __restrict__ Olo,
    int K, int N)
{
    __shared__ float t[32][33];
    int n0 = blockIdx.x * 32, k0 = blockIdx.y * 32;
    int tx = threadIdx.x & 31, ty = threadIdx.x >> 5;
    #pragma unroll
    for (int i = ty; i < 32; i += 8)
        t[i][tx] = W[(size_t)(k0 + i) * N + n0 + tx];
    __syncthreads();
    #pragma unroll
    for (int i = ty; i < 32; i += 8) {
        float v = t[tx][i];
        __nv_bfloat16 h = __float2bfloat16(v);
        float lo = v - __bfloat162float(h);
        size_t o = (size_t)(n0 + i) * K + k0 + tx;
        Ohi[o] = h;
        Olo[o] = __float2bfloat16(lo);
    }
}

// ---------------- HMMA split-bf16 GEMM ----------------
// C[M,N] = epi( A[M,K] @ Bt[N,K]^T + bias ), product = Ah*Bh + Ah*Bl + Al*Bh (fp32 acc)
// MODE 0: bias -> fp32 | MODE 2: bias+resid -> fp32 | MODE 3: bias+gelu -> bf16 hi/lo
#define LDA 40
template<int MODE>
__global__ __launch_bounds__(256, 1) void mma_gemm(
    const __nv_bfloat16* __restrict__ Ahi, const __nv_bfloat16* __restrict__ Alo,
    const __nv_bfloat16* __restrict__ Bhi, const __nv_bfloat16* __restrict__ Blo,
    const float* __restrict__ bias, const float* __restrict__ resid,
    float* __restrict__ C,
    __nv_bfloat16* __restrict__ Ohi, __nv_bfloat16* __restrict__ Olo,
    int M, int N, int K)
{
    __shared__ __nv_bfloat16 sm[4][128 * LDA];   // Ah, Al, Bh, Bl tiles (BK=32, pad 40)
    int tid = threadIdx.x, lane = tid & 31, wid = tid >> 5;
    int m0 = blockIdx.y * 128, n0 = blockIdx.x * 128;
    int wm = (wid & 1) * 64, wn = (wid >> 1) * 32;

    const __nv_bfloat16* gp0 = Ahi + (size_t)m0 * K;
    const __nv_bfloat16* gp1 = Alo + (size_t)m0 * K;
    const __nv_bfloat16* gp2 = Bhi + (size_t)n0 * K;
    const __nv_bfloat16* gp3 = Blo + (size_t)n0 * K;

    float acc[4][4][4] = {};

    int lr = tid >> 2, lc = tid & 3;           // load row (0..63) / 16B col (0..3)
    size_t off0 = (size_t)lr * K + lc * 8;
    size_t off1 = (size_t)(lr + 64) * K + lc * 8;
    uint32_t soff0 = (uint32_t)(lr * LDA + lc * 8);
    uint32_t soff1 = (uint32_t)((lr + 64) * LDA + lc * 8);

    uint32_t sb0 = smem_u32(&sm[0][0]), sb1 = smem_u32(&sm[1][0]);
    uint32_t sb2 = smem_u32(&sm[2][0]), sb3 = smem_u32(&sm[3][0]);

    uint4 st[4][2];
    st[0][0] = *(const uint4*)(gp0 + off0); st[0][1] = *(const uint4*)(gp0 + off1);
    st[1][0] = *(const uint4*)(gp1 + off0); st[1][1] = *(const uint4*)(gp1 + off1);
    st[2][0] = *(const uint4*)(gp2 + off0); st[2][1] = *(const uint4*)(gp2 + off1);
    st[3][0] = *(const uint4*)(gp3 + off0); st[3][1] = *(const uint4*)(gp3 + off1);

    // ldmatrix per-thread offsets (bytes)
    uint32_t a_off = (uint32_t)(((wm + (lane & 15)) * LDA + ((lane >> 4) << 3)) * 2);
    uint32_t b_off = (uint32_t)(((wn + ((lane >> 4) << 3) + (lane & 7)) * LDA +
                                 (((lane >> 3) & 1) << 3)) * 2);

    const int nch = K >> 5;
    for (int ch = 0; ch < nch; ch++) {
        // stage -> smem
        *(uint4*)&sm[0][soff0] = st[0][0]; *(uint4*)&sm[0][soff1] = st[0][1];
        *(uint4*)&sm[1][soff0] = st[1][0]; *(uint4*)&sm[1][soff1] = st[1][1];
        *(uint4*)&sm[2][soff0] = st[2][0]; *(uint4*)&sm[2][soff1] = st[2][1];
        *(uint4*)&sm[3][soff0] = st[3][0]; *(uint4*)&sm[3][soff1] = st[3][1];
        __syncthreads();
        // prefetch next chunk into regs (overlaps with compute below)
        if (ch + 1 < nch) {
            int kc = (ch + 1) << 5;
            st[0][0] = *(const uint4*)(gp0 + off0 + kc); st[0][1] = *(const uint4*)(gp0 + off1 + kc);
            st[1][0] = *(const uint4*)(gp1 + off0 + kc); st[1][1] = *(const uint4*)(gp1 + off1 + kc);
            st[2][0] = *(const uint4*)(gp2 + off0 + kc); st[2][1] = *(const uint4*)(gp2 + off1 + kc);
            st[3][0] = *(const uint4*)(gp3 + off0 + kc); st[3][1] = *(const uint4*)(gp3 + off1 + kc);
        }
        #pragma unroll
        for (int ks = 0; ks < 2; ks++) {
            uint32_t kb = (uint32_t)(ks * 16 * 2);
            uint32_t ah[4][4], al[4][4], bh[4][2], bl[4][2];
            #pragma unroll
            for (int mt = 0; mt < 4; mt++) {
                uint32_t o = a_off + kb + (uint32_t)(mt * 16 * LDA * 2);
                ldsm4(ah[mt][0], ah[mt][1], ah[mt][2], ah[mt][3], sb0 + o);
                ldsm4(al[mt][0], al[mt][1], al[mt][2], al[mt][3], sb1 + o);
            }
            #pragma unroll
            for (int ntp = 0; ntp < 2; ntp++) {
                uint32_t o = b_off + kb + (uint32_t)(ntp * 16 * LDA * 2);
                ldsm4(bh[2*ntp][0], bh[2*ntp][1], bh[2*ntp+1][0], bh[2*ntp+1][1], sb2 + o);
                ldsm4(bl[2*ntp][0], bl[2*ntp][1], bl[2*ntp+1][0], bl[2*ntp+1][1], sb3 + o);
            }
            #pragma unroll
            for (int mt = 0; mt < 4; mt++)
                #pragma unroll
                for (int nt = 0; nt < 4; nt++) {
                    mma16816(acc[mt][nt], ah[mt][0], ah[mt][1], ah[mt][2], ah[mt][3],
                             bh[nt][0], bh[nt][1]);
                    mma16816(acc[mt][nt], ah[mt][0], ah[mt][1], ah[mt][2], ah[mt][3],
                             bl[nt][0], bl[nt][1]);
                    mma16816(acc[mt][nt], al[mt][0], al[mt][1], al[mt][2], al[mt][3],
                             bh[nt][0], bh[nt][1]);
                }
        }
        __syncthreads();
    }

    // epilogue: direct reg -> gmem
    int er = lane >> 2, ec = (lane & 3) * 2;
    #pragma unroll
    for (int mt = 0; mt < 4; mt++) {
        #pragma unroll
        for (int nt = 0; nt < 4; nt++) {
            int m = m0 + wm + mt * 16 + er;
            int n = n0 + wn + nt * 8 + ec;
            float bv0 = bias[n], bv1 = bias[n + 1];
            float v00 = acc[mt][nt][0] + bv0, v01 = acc[mt][nt][1] + bv1;
            float v10 = acc[mt][nt][2] + bv0, v11 = acc[mt][nt][3] + bv1;
            size_t g0 = (size_t)m * N + n;
            size_t g1 = (size_t)(m + 8) * N + n;
            if (MODE == 3) {
                v00 = gelu_f(v00); v01 = gelu_f(v01);
                v10 = gelu_f(v10); v11 = gelu_f(v11);
                __nv_bfloat16 h00 = __float2bfloat16(v00), h01 = __float2bfloat16(v01);
                __nv_bfloat16 h10 = __float2bfloat16(v10), h11 = __float2bfloat16(v11);
                *(uint32_t*)(Ohi + g0) = pack_bf2(h00, h01);
                *(uint32_t*)(Ohi + g1) = pack_bf2(h10, h11);
                *(uint32_t*)(Olo + g0) = pack_bf2(
                    __float2bfloat16(v00 - __bfloat162float(h00)),
                    __float2bfloat16(v01 - __bfloat162float(h01)));
                *(uint32_t*)(Olo + g1) = pack_bf2(
                    __float2bfloat16(v10 - __bfloat162float(h10)),
                    __float2bfloat16(v11 - __bfloat162float(h11)));
            } else {
                if (MODE == 2) {
                    v00 += resid[g0]; v01 += resid[g0 + 1];
                    v10 += resid[g1]; v11 += resid[g1 + 1];
                }
                *(float2*)(C + g0) = make_float2(v00, v01);
                *(float2*)(C + g1) = make_float2(v10, v11);
            }
        }
    }
}

// ---------------- split qkv ----------------
__global__ __launch_bounds__(256) void split_qkv_kernel()
{
    int idx = blockIdx.x * 256 + threadIdx.x;
    int c = idx % (3 * Ec);
    int rowbt = idx / (3 * Ec);
    int which = c >> 10;
    int e = c & (Ec - 1);
    int h = e >> 6, d = e & 63;
    int b = rowbt >> 10, t = rowbt & (Tc - 1);
    float val = g_qkv[idx];
    float* dst = (which == 0) ? g_q : ((which == 1) ? g_k : g_v);
    dst[(((size_t)(b * Hc + h)) * Tc + t) * Dc + d] = val;
}

// ---------------- batched NT GEMM ----------------
__global__ __launch_bounds__(256) void ntgemm_kernel(
    const float* __restrict__ A, int strideA, int aModH,
    const float* __restrict__ Bm, int strideB, int bModH,
    float* __restrict__ C, size_t strideC, int M, int N, float scale)
{
    int bh = blockIdx.z;
    const float* Ab = A  + (size_t)(aModH ? (bh % Hc) : bh) * strideA;
    const float* Bb = Bm + (size_t)(bModH ? (bh % Hc) : bh) * strideB;
    float* Cb = C + (size_t)bh * strideC;
    int m0 = blockIdx.y * 64, n0 = blockIdx.x * 64;
    __shared__ float As[64][68];
    __shared__ float Bs[64][68];
    int tid = threadIdx.x;
    int tr = tid >> 4, tc4 = (tid & 15) * 4;
    #pragma unroll
    for (int p = 0; p < 4; p++) {
        int r = p * 16 + tr;
        float4 a = make_float4(0.f, 0.f, 0.f, 0.f);
        if (m0 + r < M) a = *(const float4*)(Ab + (size_t)(m0 + r) * Dc + tc4);
        As[tc4+0][r] = a.x; As[tc4+1][r] = a.y; As[tc4+2][r] = a.z; As[tc4+3][r] = a.w;
        float4 b4 = make_float4(0.f, 0.f, 0.f, 0.f);
        if (n0 + r < N) b4 = *(const float4*)(Bb + (size_t)(n0 + r) * Dc + tc4);
        Bs[tc4+0][r] = b4.x; Bs[tc4+1][r] = b4.y; Bs[tc4+2][r] = b4.z; Bs[tc4+3][r] = b4.w;
    }
    __syncthreads();
    int ty = tid >> 4, tx = tid & 15;
    float acc[4][4] = {};
    #pragma unroll
    for (int k = 0; k < 64; k++) {
        float af[4], bf[4];
        *(float4*)af = *(const float4*)&As[k][ty*4];
        *(float4*)bf = *(const float4*)&Bs[k][tx*4];
        #pragma unroll
        for (int i = 0; i < 4; i++)
            #pragma unroll
            for (int j = 0; j < 4; j++)
                acc[i][j] = fmaf(af[i], bf[j], acc[i][j]);
    }
    #pragma unroll
    for (int i = 0; i < 4; i++) {
        int m = m0 + ty*4 + i;
        if (m >= M) continue;
        #pragma unroll
        for (int j = 0; j < 4; j++) {
            int n = n0 + tx*4 + j;
            if (n < N) Cb[(size_t)m * N + n] = acc[i][j] * scale;
        }
    }
}

// ---------------- causal scores + epilogue ----------------
__global__ __launch_bounds__(256) void scores_kernel(
    const float* __restrict__ tds, const int* __restrict__ rel,
    const int* __restrict__ lrmap, const float* __restrict__ relw)
{
    int it = blockIdx.y, jt = blockIdx.x;
    if (jt > it) return;
    int bh = blockIdx.z;
    int b = bh >> 4, h = bh & 15;
    int i0 = it * 64, j0 = jt * 64;
    const float* Aq = g_q + (size_t)bh * Tc * Dc;
    const float* Bk = g_k + (size_t)bh * Tc * Dc;
    __shared__ float As[64][68];
    __shared__ float Bs[64][68];
    int tid = threadIdx.x;
    int tr = tid >> 4, tc4 = (tid & 15) * 4;
    #pragma unroll
    for (int p = 0; p < 4; p++) {
        int r = p * 16 + tr;
        float4 a = *(const float4*)(Aq + (size_t)(i0 + r) * Dc + tc4);
        As[tc4+0][r] = a.x; As[tc4+1][r] = a.y; As[tc4+2][r] = a.z; As[tc4+3][r] = a.w;
        float4 kq = *(const float4*)(Bk + (size_t)(j0 + r) * Dc + tc4);
        Bs[tc4+0][r] = kq.x; Bs[tc4+1][r] = kq.y; Bs[tc4+2][r] = kq.z; Bs[tc4+3][r] = kq.w;
    }
    __syncthreads();
    int ty = tid >> 4, tx = tid & 15;
    float acc[4][4] = {};
    #pragma unroll
    for (int k = 0; k < 64; k++) {
        float af[4], bf[4];
        *(float4*)af = *(const float4*)&As[k][ty*4];
        *(float4*)bf = *(const float4*)&Bs[k][tx*4];
        #pragma unroll
        for (int i = 0; i < 4; i++)
            #pragma unroll
            for (int j = 0; j < 4; j++)
                acc[i][j] = fmaf(af[i], bf[j], acc[i][j]);
    }
    #pragma unroll
    for (int ii = 0; ii < 4; ii++) {
        int i = i0 + ty*4 + ii;
        const float* qrk_row = g_qrk + ((size_t)bh * Tc + i) * 65;
        const float* lr1_row = g_lr1 + ((size_t)bh * Tc + i) * NRELc;
        size_t base_b  = ((size_t)b  * Tc + i) * Tc;
        size_t base_bh = ((size_t)bh * Tc + i) * Tc;
        #pragma unroll
        for (int jj = 0; jj < 4; jj++) {
            int j = j0 + tx*4 + jj;
            if (j > i) continue;
            int rid = j - i + 32; if (rid < 0) rid = 0;
            float wv = (acc[ii][jj] + qrk_row[rid]) * INV_SQRT_D;
            wv *= relw[rel[base_b + j] * Hc + h];
            wv += tds[base_bh + j];
            int lm = lrmap[base_b + j];
            wv = (wv + lr1_row[lm] + g_lr2[((size_t)bh * NRELc + lm) * Tc + j]) * INV_SQRT3;
            g_w[base_bh + j] = wv;
        }
    }
}

// ---------------- causal softmax ----------------
__global__ __launch_bounds__(128) void softmax_kernel()
{
    int row = blockIdx.x;
    int i = row & (Tc - 1);
    float* wr = g_w + (size_t)row * Tc;
    int len = i + 1;
    int wid = threadIdx.x >> 5, lane = threadIdx.x & 31;
    __shared__ float sm[4], sm2[4];

    float mx = -1e30f;
    for (int j = threadIdx.x; j < len; j += 128) mx = fmaxf(mx, wr[j]);
    mx = warp_max(mx);
    if (lane == 0) sm[wid] = mx;
    __syncthreads();
    mx = fmaxf(fmaxf(sm[0], sm[1]), fmaxf(sm[2], sm[3]));

    float s = 0.f;
    for (int j = threadIdx.x; j < len; j += 128) {
        float e = __expf(wr[j] - mx);
        wr[j] = e;
        s += e;
    }
    s = warp_sum(s);
    if (lane == 0) sm2[wid] = s;
    __syncthreads();
    float inv = 1.f / (sm2[0] + sm2[1] + sm2[2] + sm2[3]);
    for (int j = threadIdx.x; j < len; j += 128) wr[j] *= inv;
}

// ---------------- causal p @ v ----------------
__global__ __launch_bounds__(256) void pv_kernel()
{
    int bh = blockIdx.z;
    int it = blockIdx.y;
    int i0 = it * 64;
    __shared__ float Ps[64][68];
    __shared__ float Vs[64][68];
    int tid = threadIdx.x;
    int tr = tid >> 4, tc4 = (tid & 15) * 4;
    int ty = tid >> 4, tx = tid & 15;
    float acc[4][4] = {};
    const float* Vb = g_v + (size_t)bh * Tc * Dc;

    for (int jt = 0; jt <= it; jt++) {
        int j0 = jt * 64;
        #pragma unroll
        for (int p = 0; p < 4; p++) {
            int r = p * 16 + tr;
            int i = i0 + r;
            float4 pv4 = *(const float4*)(g_w + ((size_t)bh * Tc + i) * Tc + j0 + tc4);
            int jb = j0 + tc4;
            Ps[tc4+0][r] = (jb + 0 <= i) ? pv4.x : 0.f;
            Ps[tc4+1][r] = (jb + 1 <= i) ? pv4.y : 0.f;
            Ps[tc4+2][r] = (jb + 2 <= i) ? pv4.z : 0.f;
            Ps[tc4+3][r] = (jb + 3 <= i) ? pv4.w : 0.f;
            float4 vv = *(const float4*)(Vb + (size_t)(j0 + r) * Dc + tc4);
            *(float4*)&Vs[r][tc4] = vv;
        }
        __syncthreads();
        #pragma unroll
        for (int k = 0; k < 64; k++) {
            float af[4], bf[4];
            *(float4*)af = *(const float4*)&Ps[k][ty*4];
            *(float4*)bf = *(const float4*)&Vs[k][tx*4];
            #pragma unroll
            for (int i2 = 0; i2 < 4; i2++)
                #pragma unroll
                for (int j2 = 0; j2 < 4; j2++)
                    acc[i2][j2] = fmaf(af[i2], bf[j2], acc[i2][j2]);
        }
        __syncthreads();
    }
    #pragma unroll
    for (int i2 = 0; i2 < 4; i2++)
        #pragma unroll
        for (int j2 = 0; j2 < 4; j2++)
            g_ret[((size_t)bh * Tc + i0 + ty*4 + i2) * Dc + tx*4 + j2] = acc[i2][j2];
}

// ---------------- relv term + merge heads -> split-bf16 actA ----------------
__global__ __launch_bounds__(64) void relv_merge_kernel(const float* __restrict__ rv)
{
    int row = blockIdx.x;
    int i = row & (Tc - 1);
    int bh = row >> 10;
    int b = bh >> 4, hd = bh & 15;
    __shared__ float pl[32];
    if (threadIdx.x < 32) {
        int j = i - 31 + (int)threadIdx.x;
        pl[threadIdx.x] = (j >= 0) ? g_w[(size_t)row * Tc + j] : 0.f;
    }
    __syncthreads();
    int d = threadIdx.x;
    float s32 = 0.f, contrib = 0.f;
    #pragma unroll
    for (int l = 0; l < 32; l++) {
        float p = pl[l];
        s32 += p;
        contrib = fmaf(p, rv[(l + 1) * Dc + d], contrib);
    }
    contrib = fmaf(1.f - s32, rv[d], contrib);
    float val = g_ret[(size_t)row * Dc + d] + contrib;
    size_t o = ((size_t)(b * Tc + i)) * Ec + hd * Dc + d;
    __nv_bfloat16 h = __float2bfloat16(val);
    g_actA_hi[o] = h;
    g_actA_lo[o] = __float2bfloat16(val - __bfloat162float(h));
}

// ---------------- host ----------------
extern "C" void kernel_launch(void* const* d_in, const int* in_sizes, int n_in,
                              void* d_out, int out_size)
{
    int ix, itds, ilrq, ilrk, irel, ilrm, iwqkv, ibqkv, iwpr, ibpr, irlw, irlk, irlv,
        il1w, il1b, il2w, il2b, iwfc, ibfc, iwfp, ibfp;
    if (in_sizes[4] == 3 * 1024 * 1024) {
        ix=0; itds=1; ilrq=2; ilrk=3; iwqkv=4; ibqkv=5; iwpr=6; ibpr=7; irlw=8; irlk=9; irlv=10;
        il1w=11; il1b=12; il2w=13; il2b=14; iwfc=15; ibfc=16; iwfp=17; ibfp=18; irel=19; ilrm=20;
    } else {
        ix=0; itds=1; ilrq=2; ilrk=3; irel=4; ilrm=5; iwqkv=6; ibqkv=7; iwpr=8; ibpr=9; irlw=10;
        irlk=11; irlv=12; il1w=13; il1b=14; il2w=15; il2b=16; iwfc=17; ibfc=18; iwfp=19; ibfp=20;
    }
    const float* x    = (const float*)d_in[ix];
    const float* tds  = (const float*)d_in[itds];
    const float* LRQ  = (const float*)d_in[ilrq];
    const float* LRK  = (const float*)d_in[ilrk];
    const int*   rel  = (const int*)  d_in[irel];
    const int*   lrm  = (const int*)  d_in[ilrm];
    const float* Wqkv = (const float*)d_in[iwqkv];
    const float* bqkv = (const float*)d_in[ibqkv];
    const float* Wpr  = (const float*)d_in[iwpr];
    const float* bpr  = (const float*)d_in[ibpr];
    const float* relw = (const float*)d_in[irlw];
    const float* relk = (const float*)d_in[irlk];
    const float* relv = (const float*)d_in[irlv];
    const float* l1w  = (const float*)d_in[il1w];
    const float* l1b  = (const float*)d_in[il1b];
    const float* l2w  = (const float*)d_in[il2w];
    const float* l2b  = (const float*)d_in[il2b];
    const float* Wfc  = (const float*)d_in[iwfc];
    const float* bfc  = (const float*)d_in[ibfc];
    const float* Wfp  = (const float*)d_in[iwfp];
    const float* bfp  = (const float*)d_in[ibfp];
    float* out = (float*)d_out;

    float *p_qkv, *p_q, *p_k, *p_qrk, *p_lr1, *p_lr2, *p_x2;
    __nv_bfloat16 *aAh, *aAl, *aBh, *aBl, *wth, *wtl;
    cudaGetSymbolAddress((void**)&p_qkv, g_qkv);
    cudaGetSymbolAddress((void**)&p_q,   g_q);
    cudaGetSymbolAddress((void**)&p_k,   g_k);
    cudaGetSymbolAddress((void**)&p_qrk, g_qrk);
    cudaGetSymbolAddress((void**)&p_lr1, g_lr1);
    cudaGetSymbolAddress((void**)&p_lr2, g_lr2);
    cudaGetSymbolAddress((void**)&p_x2,  g_x2);
    cudaGetSymbolAddress((void**)&aAh,   g_actA_hi);
    cudaGetSymbolAddress((void**)&aAl,   g_actA_lo);
    cudaGetSymbolAddress((void**)&aBh,   g_actB_hi);
    cudaGetSymbolAddress((void**)&aBl,   g_actB_lo);
    cudaGetSymbolAddress((void**)&wth,   g_wt_hi);
    cudaGetSymbolAddress((void**)&wtl,   g_wt_lo);

    const int M = Bc * Tc;   // 2048

    // weight transpose/convert
    transpose_conv_kernel<<<dim3(96, 32),  256>>>(Wqkv, wth + WOFF_QKV,  wtl + WOFF_QKV,  1024, 3072);
    transpose_conv_kernel<<<dim3(32, 32),  256>>>(Wpr,  wth + WOFF_PROJ, wtl + WOFF_PROJ, 1024, 1024);
    transpose_conv_kernel<<<dim3(128, 32), 256>>>(Wfc,  wth + WOFF_FC,   wtl + WOFF_FC,   1024, 4096);
    transpose_conv_kernel<<<dim3(32, 128), 256>>>(Wfp,  wth + WOFF_FP,   wtl + WOFF_FP,   4096, 1024);

    // 1) LN1 -> split bf16
    ln_bf16_kernel<<<M, 256>>>(x, l1w, l1b, aAh, aAl);
    // 2) QKV via HMMA -> fp32, then split heads
    mma_gemm<0><<<dim3(24, 16), 256>>>(aAh, aAl, wth + WOFF_QKV, wtl + WOFF_QKV,
                                       bqkv, nullptr, p_qkv, nullptr, nullptr, M, 3072, 1024);
    split_qkv_kernel<<<(Bc*Tc*3*Ec)/256, 256>>>();
    // 3) qrk / lr1 / lr2
    ntgemm_kernel<<<dim3(2, Tc/64, BHc), 256>>>(p_q, Tc*Dc, 0, relk, 0, 0,
                                                p_qrk, (size_t)Tc*65, Tc, 65, 1.0f);
    ntgemm_kernel<<<dim3((NRELc+63)/64, Tc/64, BHc), 256>>>(p_q, Tc*Dc, 0, LRK, NRELc*Dc, 1,
                                                p_lr1, (size_t)Tc*NRELc, Tc, NRELc, INV_SQRT_D);
    ntgemm_kernel<<<dim3(Tc/64, (NRELc+63)/64, BHc), 256>>>(LRQ, NRELc*Dc, 1, p_k, Tc*Dc, 0,
                                                p_lr2, (size_t)NRELc*Tc, NRELc, Tc, INV_SQRT_D);
    // 4) scores + softmax + p@v + relv/merge
    scores_kernel<<<dim3(Tc/64, Tc/64, BHc), 256>>>(tds, rel, lrm, relw);
    softmax_kernel<<<BHc*Tc, 128>>>();
    pv_kernel<<<dim3(1, Tc/64, BHc), 256>>>();
    relv_merge_kernel<<<BHc*Tc, 64>>>(relv);
    // 5) proj + residual
    mma_gemm<2><<<dim3(8, 16), 256>>>(aAh, aAl, wth + WOFF_PROJ, wtl + WOFF_PROJ,
                                      bpr, x, p_x2, nullptr, nullptr, M, 1024, 1024);
    // 6) LN2 -> split bf16
    ln_bf16_kernel<<<M, 256>>>(p_x2, l2w, l2b, aAh, aAl);
    // 7) FC + gelu -> split bf16
    mma_gemm<3><<<dim3(32, 16), 256>>>(aAh, aAl, wth + WOFF_FC, wtl + WOFF_FC,
                                       bfc, nullptr, nullptr, aBh, aBl, M, 4096, 1024);
    // 8) FP + bias + residual -> out
    mma_gemm<2><<<dim3(8, 16), 256>>>(aBh, aBl, wth + WOFF_FP, wtl + WOFF_FP,
                                      bfp, p_x2, out, nullptr, nullptr, M, 1024, 4096);
}